// round 4
// baseline (speedup 1.0000x reference)
#include <cuda_runtime.h>

#define FDIM 128
#define S_N 50000
#define T_N 50000
#define E_N 600000
#define F2 256
#define F4 512
#define SLOPE 0.1f
#define BN_EPS 1e-5f

#define BM 64
#define BN 64
#define BK 16

// Scratch (device globals — no runtime allocation allowed)
__device__ float  g_aggH[(size_t)T_N * F2];  // sum of leaky(layer1 out) per target
__device__ float  g_aggB[(size_t)T_N * F2];  // agg after W1b + cnt*b1b
__device__ float  g_h3[(size_t)T_N * F4];    // leaky(node layer1 out)
__device__ int    g_cnt[T_N];
__device__ double g_sum[FDIM];
__device__ double g_sumsq[FDIM];

__global__ void zero_kernel() {
    int idx = blockIdx.x * blockDim.x + threadIdx.x;
    int stride = gridDim.x * blockDim.x;
    for (size_t i = idx; i < (size_t)T_N * F2; i += stride) g_aggH[i] = 0.f;
    for (int i = idx; i < T_N; i += stride) g_cnt[i] = 0;
    if (idx < FDIM) { g_sum[idx] = 0.0; g_sumsq[idx] = 0.0; }
}

// ---------------------------------------------------------------------------
// GEMM 1: [E,256](gathered) @ W1a[256,256], epilogue: +b1a, leaky, atomic
// scatter-add into g_aggH[tgt]. Also counts edges per target (col-block 0).
// ---------------------------------------------------------------------------
__global__ void __launch_bounds__(256) gemm_edge(
    const float* __restrict__ x_s, const float* __restrict__ edge_attr,
    const int* __restrict__ eidx,
    const float* __restrict__ W1a, const float* __restrict__ b1a)
{
    __shared__ __align__(16) float As[BK][BM + 4];
    __shared__ __align__(16) float Bs[BK][BN + 4];
    __shared__ int sSrc[BM];
    __shared__ int sTgt[BM];

    int tid = threadIdx.x;
    int m0 = blockIdx.y * BM;
    int n0 = blockIdx.x * BN;

    if (tid < BM) {
        int m = m0 + tid;                 // E_N divisible by BM
        sSrc[tid] = eidx[m];
        sTgt[tid] = eidx[E_N + m];
    }
    __syncthreads();
    if (blockIdx.x == 0 && tid < BM) atomicAdd(&g_cnt[sTgt[tid]], 1);

    float acc[4][4] = {};
    int ty = tid >> 4, tx = tid & 15;
    int ai = tid >> 2, akq = (tid & 3) * 4;   // A-tile: one float4 per thread
    int bk = tid >> 4, bn = (tid & 15) * 4;   // B-tile: one float4 per thread

    for (int kt = 0; kt < F2; kt += BK) {
        int gk = kt + akq;
        const float* ap;
        if (gk < FDIM) ap = x_s + (size_t)sSrc[ai] * FDIM + gk;
        else           ap = edge_attr + (size_t)(m0 + ai) * FDIM + (gk - FDIM);
        float4 av = *reinterpret_cast<const float4*>(ap);
        As[akq + 0][ai] = av.x; As[akq + 1][ai] = av.y;
        As[akq + 2][ai] = av.z; As[akq + 3][ai] = av.w;

        float4 bv = *reinterpret_cast<const float4*>(W1a + (size_t)(kt + bk) * F2 + n0 + bn);
        *reinterpret_cast<float4*>(&Bs[bk][bn]) = bv;
        __syncthreads();

        #pragma unroll
        for (int kk = 0; kk < BK; kk++) {
            float4 a = *reinterpret_cast<const float4*>(&As[kk][ty * 4]);
            float4 b = *reinterpret_cast<const float4*>(&Bs[kk][tx * 4]);
            float ar[4] = {a.x, a.y, a.z, a.w};
            float br[4] = {b.x, b.y, b.z, b.w};
            #pragma unroll
            for (int i = 0; i < 4; i++)
                #pragma unroll
                for (int j = 0; j < 4; j++)
                    acc[i][j] = fmaf(ar[i], br[j], acc[i][j]);
        }
        __syncthreads();
    }

    #pragma unroll
    for (int i = 0; i < 4; i++) {
        int t = sTgt[ty * 4 + i];
        #pragma unroll
        for (int j = 0; j < 4; j++) {
            int n = n0 + tx * 4 + j;
            float v = acc[i][j] + b1a[n];
            v = v >= 0.f ? v : SLOPE * v;
            atomicAdd(&g_aggH[(size_t)t * F2 + n], v);
        }
    }
}

// ---------------------------------------------------------------------------
// GEMM 2: g_aggH[T,256] @ W1b[256,256], epilogue: + cnt[m]*b1b -> g_aggB
// ---------------------------------------------------------------------------
__global__ void __launch_bounds__(256) gemm_mid(
    const float* __restrict__ W1b, const float* __restrict__ b1b)
{
    __shared__ __align__(16) float As[BK][BM + 4];
    __shared__ __align__(16) float Bs[BK][BN + 4];

    int tid = threadIdx.x;
    int m0 = blockIdx.y * BM;
    int n0 = blockIdx.x * BN;

    float acc[4][4] = {};
    int ty = tid >> 4, tx = tid & 15;
    int ai = tid >> 2, akq = (tid & 3) * 4;
    int bk = tid >> 4, bn = (tid & 15) * 4;

    for (int kt = 0; kt < F2; kt += BK) {
        int r = m0 + ai;
        float4 av = make_float4(0.f, 0.f, 0.f, 0.f);
        if (r < T_N)
            av = *reinterpret_cast<const float4*>(&g_aggH[(size_t)r * F2 + kt + akq]);
        As[akq + 0][ai] = av.x; As[akq + 1][ai] = av.y;
        As[akq + 2][ai] = av.z; As[akq + 3][ai] = av.w;

        float4 bv = *reinterpret_cast<const float4*>(W1b + (size_t)(kt + bk) * F2 + n0 + bn);
        *reinterpret_cast<float4*>(&Bs[bk][bn]) = bv;
        __syncthreads();

        #pragma unroll
        for (int kk = 0; kk < BK; kk++) {
            float4 a = *reinterpret_cast<const float4*>(&As[kk][ty * 4]);
            float4 b = *reinterpret_cast<const float4*>(&Bs[kk][tx * 4]);
            float ar[4] = {a.x, a.y, a.z, a.w};
            float br[4] = {b.x, b.y, b.z, b.w};
            #pragma unroll
            for (int i = 0; i < 4; i++)
                #pragma unroll
                for (int j = 0; j < 4; j++)
                    acc[i][j] = fmaf(ar[i], br[j], acc[i][j]);
        }
        __syncthreads();
    }

    #pragma unroll
    for (int i = 0; i < 4; i++) {
        int r = m0 + ty * 4 + i;
        if (r >= T_N) continue;
        float c = (float)g_cnt[r];
        #pragma unroll
        for (int j = 0; j < 4; j++) {
            int n = n0 + tx * 4 + j;
            g_aggB[(size_t)r * F2 + n] = acc[i][j] + c * b1b[n];
        }
    }
}

// ---------------------------------------------------------------------------
// GEMM 3: [T,512](= x_t | aggB | u) @ W2a[512,512], epilogue +b2a, leaky -> g_h3
// ---------------------------------------------------------------------------
__global__ void __launch_bounds__(256) gemm_node1(
    const float* __restrict__ x_t, const float* __restrict__ u,
    const float* __restrict__ W2a, const float* __restrict__ b2a)
{
    __shared__ __align__(16) float As[BK][BM + 4];
    __shared__ __align__(16) float Bs[BK][BN + 4];

    int tid = threadIdx.x;
    int m0 = blockIdx.y * BM;
    int n0 = blockIdx.x * BN;

    float acc[4][4] = {};
    int ty = tid >> 4, tx = tid & 15;
    int ai = tid >> 2, akq = (tid & 3) * 4;
    int bk = tid >> 4, bn = (tid & 15) * 4;

    for (int kt = 0; kt < F4; kt += BK) {
        int r = m0 + ai;
        int gk = kt + akq;
        float4 av = make_float4(0.f, 0.f, 0.f, 0.f);
        if (r < T_N) {
            if (gk < FDIM)
                av = *reinterpret_cast<const float4*>(x_t + (size_t)r * FDIM + gk);
            else if (gk < FDIM + F2)
                av = *reinterpret_cast<const float4*>(&g_aggB[(size_t)r * F2 + gk - FDIM]);
            else
                av = *reinterpret_cast<const float4*>(u + (gk - FDIM - F2));
        }
        As[akq + 0][ai] = av.x; As[akq + 1][ai] = av.y;
        As[akq + 2][ai] = av.z; As[akq + 3][ai] = av.w;

        float4 bv = *reinterpret_cast<const float4*>(W2a + (size_t)(kt + bk) * F4 + n0 + bn);
        *reinterpret_cast<float4*>(&Bs[bk][bn]) = bv;
        __syncthreads();

        #pragma unroll
        for (int kk = 0; kk < BK; kk++) {
            float4 a = *reinterpret_cast<const float4*>(&As[kk][ty * 4]);
            float4 b = *reinterpret_cast<const float4*>(&Bs[kk][tx * 4]);
            float ar[4] = {a.x, a.y, a.z, a.w};
            float br[4] = {b.x, b.y, b.z, b.w};
            #pragma unroll
            for (int i = 0; i < 4; i++)
                #pragma unroll
                for (int j = 0; j < 4; j++)
                    acc[i][j] = fmaf(ar[i], br[j], acc[i][j]);
        }
        __syncthreads();
    }

    #pragma unroll
    for (int i = 0; i < 4; i++) {
        int r = m0 + ty * 4 + i;
        if (r >= T_N) continue;
        #pragma unroll
        for (int j = 0; j < 4; j++) {
            int n = n0 + tx * 4 + j;
            float v = acc[i][j] + b2a[n];
            v = v >= 0.f ? v : SLOPE * v;
            g_h3[(size_t)r * F4 + n] = v;
        }
    }
}

// ---------------------------------------------------------------------------
// GEMM 4: g_h3[T,512] @ W2b[512,128], epilogue +b2b -> out (pre-BN y)
// ---------------------------------------------------------------------------
__global__ void __launch_bounds__(256) gemm_node2(
    const float* __restrict__ W2b, const float* __restrict__ b2b,
    float* __restrict__ out)
{
    __shared__ __align__(16) float As[BK][BM + 4];
    __shared__ __align__(16) float Bs[BK][BN + 4];

    int tid = threadIdx.x;
    int m0 = blockIdx.y * BM;
    int n0 = blockIdx.x * BN;

    float acc[4][4] = {};
    int ty = tid >> 4, tx = tid & 15;
    int ai = tid >> 2, akq = (tid & 3) * 4;
    int bk = tid >> 4, bn = (tid & 15) * 4;

    for (int kt = 0; kt < F4; kt += BK) {
        int r = m0 + ai;
        float4 av = make_float4(0.f, 0.f, 0.f, 0.f);
        if (r < T_N)
            av = *reinterpret_cast<const float4*>(&g_h3[(size_t)r * F4 + kt + akq]);
        As[akq + 0][ai] = av.x; As[akq + 1][ai] = av.y;
        As[akq + 2][ai] = av.z; As[akq + 3][ai] = av.w;

        float4 bv = *reinterpret_cast<const float4*>(W2b + (size_t)(kt + bk) * FDIM + n0 + bn);
        *reinterpret_cast<float4*>(&Bs[bk][bn]) = bv;
        __syncthreads();

        #pragma unroll
        for (int kk = 0; kk < BK; kk++) {
            float4 a = *reinterpret_cast<const float4*>(&As[kk][ty * 4]);
            float4 b = *reinterpret_cast<const float4*>(&Bs[kk][tx * 4]);
            float ar[4] = {a.x, a.y, a.z, a.w};
            float br[4] = {b.x, b.y, b.z, b.w};
            #pragma unroll
            for (int i = 0; i < 4; i++)
                #pragma unroll
                for (int j = 0; j < 4; j++)
                    acc[i][j] = fmaf(ar[i], br[j], acc[i][j]);
        }
        __syncthreads();
    }

    #pragma unroll
    for (int i = 0; i < 4; i++) {
        int r = m0 + ty * 4 + i;
        if (r >= T_N) continue;
        #pragma unroll
        for (int j = 0; j < 4; j++) {
            int n = n0 + tx * 4 + j;
            out[(size_t)r * FDIM + n] = acc[i][j] + b2b[n];
        }
    }
}

// ---------------------------------------------------------------------------
// BatchNorm: column stats (double accum) then normalize in place
// ---------------------------------------------------------------------------
__global__ void bn_stats(const float* __restrict__ y) {
    int c = threadIdx.x & (FDIM - 1);
    int half = threadIdx.x >> 7;
    double s = 0.0, sq = 0.0;
    for (int m = blockIdx.x * 2 + half; m < T_N; m += gridDim.x * 2) {
        float v = y[(size_t)m * FDIM + c];
        s += v;
        sq += (double)v * (double)v;
    }
    atomicAdd(&g_sum[c], s);
    atomicAdd(&g_sumsq[c], sq);
}

__global__ void bn_norm(float* __restrict__ y,
                        const float* __restrict__ gamma,
                        const float* __restrict__ beta) {
    size_t idx = (size_t)blockIdx.x * blockDim.x + threadIdx.x;
    if (idx >= (size_t)T_N * FDIM) return;
    int c = (int)(idx & (FDIM - 1));
    double mean = g_sum[c] / (double)T_N;
    double var = g_sumsq[c] / (double)T_N - mean * mean;
    float scale = rsqrtf((float)var + BN_EPS) * gamma[c];
    y[idx] = (float)((double)y[idx] - mean) * scale + beta[c];
}

extern "C" void kernel_launch(void* const* d_in, const int* in_sizes, int n_in,
                              void* d_out, int out_size) {
    const float* x_s       = (const float*)d_in[0];
    const float* x_t       = (const float*)d_in[1];
    const float* edge_attr = (const float*)d_in[2];
    const float* u         = (const float*)d_in[3];
    const int*   eidx      = (const int*)d_in[4];
    const float* W1a       = (const float*)d_in[5];
    const float* b1a       = (const float*)d_in[6];
    const float* W1b       = (const float*)d_in[7];
    const float* b1b       = (const float*)d_in[8];
    const float* W2a       = (const float*)d_in[9];
    const float* b2a       = (const float*)d_in[10];
    const float* W2b       = (const float*)d_in[11];
    const float* b2b       = (const float*)d_in[12];
    const float* gamma     = (const float*)d_in[13];
    const float* beta      = (const float*)d_in[14];
    float* out = (float*)d_out;

    zero_kernel<<<1024, 256>>>();

    dim3 gE(F2 / BN, E_N / BM);                 // (4, 9375)
    gemm_edge<<<gE, 256>>>(x_s, edge_attr, eidx, W1a, b1a);

    int mblk = (T_N + BM - 1) / BM;             // 782
    dim3 gM(F2 / BN, mblk);
    gemm_mid<<<gM, 256>>>(W1b, b1b);

    dim3 gN1(F4 / BN, mblk);
    gemm_node1<<<gN1, 256>>>(x_t, u, W2a, b2a);

    dim3 gN2(FDIM / BN, mblk);
    gemm_node2<<<gN2, 256>>>(W2b, b2b, out);

    bn_stats<<<512, 256>>>(out);
    bn_norm<<<(T_N * FDIM + 255) / 256, 256>>>(out, gamma, beta);
}

// round 6
// speedup vs baseline: 1.5653x; 1.5653x over previous
#include <cuda_runtime.h>

#define FDIM 128
#define S_N 50000
#define T_N 50000
#define E_N 600000
#define F2 256
#define F4 512
#define SLOPE 0.1f
#define BN_EPS 1e-5f

#define BM 64
#define BN 64
#define BK 16

// Scratch (device globals — no runtime allocation allowed)
__device__ float  g_P[(size_t)S_N * F2];     // x_s @ W1a_top + b1a
__device__ float  g_aggH[(size_t)T_N * F2];  // sum of leaky(layer1 out) per target
__device__ float  g_h3[(size_t)T_N * F4];    // leaky(node layer1 out)
__device__ float  g_Wmid[(size_t)F2 * F4];   // W1b @ W2a[128:384]
__device__ float  g_bvec[F4];                // b1b @ W2a[128:384]
__device__ float  g_c2[F4];                  // u @ W2a[384:512] + b2a
__device__ int    g_cnt[T_N];
__device__ double g_sum[FDIM];
__device__ double g_sumsq[FDIM];

__global__ void zero_kernel() {
    int idx = blockIdx.x * blockDim.x + threadIdx.x;
    int stride = gridDim.x * blockDim.x;
    for (size_t i = idx; i < (size_t)T_N * F2; i += stride) g_aggH[i] = 0.f;
    for (int i = idx; i < T_N; i += stride) g_cnt[i] = 0;
    if (idx < FDIM) { g_sum[idx] = 0.0; g_sumsq[idx] = 0.0; }
}

// ---------------------------------------------------------------------------
// Wmid[k][j] = sum_m W1b[k][m] * W2a[128+m][j]   (256 x 512)
// ---------------------------------------------------------------------------
__global__ void __launch_bounds__(512) compute_Wmid(
    const float* __restrict__ W1b, const float* __restrict__ W2a)
{
    __shared__ float sRow[F2];
    int k = blockIdx.x;
    int j = threadIdx.x;
    if (j < F2) sRow[j] = W1b[(size_t)k * F2 + j];
    __syncthreads();
    float acc = 0.f;
    #pragma unroll 4
    for (int m = 0; m < F2; m++)
        acc = fmaf(sRow[m], W2a[(size_t)(128 + m) * F4 + j], acc);
    g_Wmid[(size_t)k * F4 + j] = acc;
}

// ---------------------------------------------------------------------------
// bvec[j] = sum_m b1b[m]*W2a[128+m][j];  c2[j] = b2a[j] + sum_k u[k]*W2a[384+k][j]
// ---------------------------------------------------------------------------
__global__ void __launch_bounds__(512) compute_vecs(
    const float* __restrict__ b1b, const float* __restrict__ u,
    const float* __restrict__ W2a, const float* __restrict__ b2a)
{
    int j = threadIdx.x;
    float bv = 0.f;
    for (int m = 0; m < F2; m++)
        bv = fmaf(b1b[m], W2a[(size_t)(128 + m) * F4 + j], bv);
    g_bvec[j] = bv;
    float cv = b2a[j];
    for (int k = 0; k < FDIM; k++)
        cv = fmaf(u[k], W2a[(size_t)(384 + k) * F4 + j], cv);
    g_c2[j] = cv;
}

// ---------------------------------------------------------------------------
// P = x_s[S,128] @ W1a[0:128][256] + b1a  -> g_P
// ---------------------------------------------------------------------------
__global__ void __launch_bounds__(256) gemm_pre(
    const float* __restrict__ x_s,
    const float* __restrict__ W1a, const float* __restrict__ b1a)
{
    __shared__ __align__(16) float As[BK][BM + 4];
    __shared__ __align__(16) float Bs[BK][BN + 4];

    int tid = threadIdx.x;
    int m0 = blockIdx.y * BM;
    int n0 = blockIdx.x * BN;

    float acc[4][4] = {};
    int ty = tid >> 4, tx = tid & 15;
    int ai = tid >> 2, akq = (tid & 3) * 4;
    int bk = tid >> 4, bn = (tid & 15) * 4;

    for (int kt = 0; kt < FDIM; kt += BK) {
        int r = m0 + ai;
        float4 av = make_float4(0.f, 0.f, 0.f, 0.f);
        if (r < S_N)
            av = *reinterpret_cast<const float4*>(x_s + (size_t)r * FDIM + kt + akq);
        As[akq + 0][ai] = av.x; As[akq + 1][ai] = av.y;
        As[akq + 2][ai] = av.z; As[akq + 3][ai] = av.w;

        float4 bv = *reinterpret_cast<const float4*>(W1a + (size_t)(kt + bk) * F2 + n0 + bn);
        *reinterpret_cast<float4*>(&Bs[bk][bn]) = bv;
        __syncthreads();

        #pragma unroll
        for (int kk = 0; kk < BK; kk++) {
            float4 a = *reinterpret_cast<const float4*>(&As[kk][ty * 4]);
            float4 b = *reinterpret_cast<const float4*>(&Bs[kk][tx * 4]);
            float ar[4] = {a.x, a.y, a.z, a.w};
            float br[4] = {b.x, b.y, b.z, b.w};
            #pragma unroll
            for (int i = 0; i < 4; i++)
                #pragma unroll
                for (int j = 0; j < 4; j++)
                    acc[i][j] = fmaf(ar[i], br[j], acc[i][j]);
        }
        __syncthreads();
    }

    #pragma unroll
    for (int i = 0; i < 4; i++) {
        int r = m0 + ty * 4 + i;
        if (r >= S_N) continue;
        #pragma unroll
        for (int j = 0; j < 4; j++) {
            int n = n0 + tx * 4 + j;
            g_P[(size_t)r * F2 + n] = acc[i][j] + b1a[n];
        }
    }
}

// ---------------------------------------------------------------------------
// Edge GEMM: edge_attr[E,128] @ W1a[128:256][256]; epilogue:
//   v = leaky(acc + P[src][n]); atomicAdd aggH[tgt][n]. Counts in col-block 0.
// ---------------------------------------------------------------------------
__global__ void __launch_bounds__(256) gemm_edge(
    const float* __restrict__ edge_attr, const int* __restrict__ eidx,
    const float* __restrict__ W1a)
{
    __shared__ __align__(16) float As[BK][BM + 4];
    __shared__ __align__(16) float Bs[BK][BN + 4];
    __shared__ int sSrc[BM];
    __shared__ int sTgt[BM];

    int tid = threadIdx.x;
    int m0 = blockIdx.y * BM;
    int n0 = blockIdx.x * BN;

    if (tid < BM) {
        int m = m0 + tid;                 // E_N divisible by BM
        sSrc[tid] = eidx[m];
        sTgt[tid] = eidx[E_N + m];
    }
    __syncthreads();
    if (blockIdx.x == 0 && tid < BM) atomicAdd(&g_cnt[sTgt[tid]], 1);

    float acc[4][4] = {};
    int ty = tid >> 4, tx = tid & 15;
    int ai = tid >> 2, akq = (tid & 3) * 4;
    int bk = tid >> 4, bn = (tid & 15) * 4;

    for (int kt = 0; kt < FDIM; kt += BK) {
        float4 av = *reinterpret_cast<const float4*>(
            edge_attr + (size_t)(m0 + ai) * FDIM + kt + akq);
        As[akq + 0][ai] = av.x; As[akq + 1][ai] = av.y;
        As[akq + 2][ai] = av.z; As[akq + 3][ai] = av.w;

        float4 bv = *reinterpret_cast<const float4*>(
            W1a + (size_t)(FDIM + kt + bk) * F2 + n0 + bn);
        *reinterpret_cast<float4*>(&Bs[bk][bn]) = bv;
        __syncthreads();

        #pragma unroll
        for (int kk = 0; kk < BK; kk++) {
            float4 a = *reinterpret_cast<const float4*>(&As[kk][ty * 4]);
            float4 b = *reinterpret_cast<const float4*>(&Bs[kk][tx * 4]);
            float ar[4] = {a.x, a.y, a.z, a.w};
            float br[4] = {b.x, b.y, b.z, b.w};
            #pragma unroll
            for (int i = 0; i < 4; i++)
                #pragma unroll
                for (int j = 0; j < 4; j++)
                    acc[i][j] = fmaf(ar[i], br[j], acc[i][j]);
        }
        __syncthreads();
    }

    #pragma unroll
    for (int i = 0; i < 4; i++) {
        int row = ty * 4 + i;
        int s = sSrc[row];
        int t = sTgt[row];
        float4 pv = *reinterpret_cast<const float4*>(&g_P[(size_t)s * F2 + n0 + tx * 4]);
        float pr[4] = {pv.x, pv.y, pv.z, pv.w};
        #pragma unroll
        for (int j = 0; j < 4; j++) {
            float v = acc[i][j] + pr[j];
            v = v >= 0.f ? v : SLOPE * v;
            atomicAdd(&g_aggH[(size_t)t * F2 + n0 + tx * 4 + j], v);
        }
    }
}

// ---------------------------------------------------------------------------
// Node GEMM 1: [T,384](= x_t | aggH) @ [W2a_top ; Wmid] (384x512)
// epilogue: v = leaky(acc + c2[n] + cnt[r]*bvec[n]) -> g_h3
// ---------------------------------------------------------------------------
__global__ void __launch_bounds__(256) gemm_node1(
    const float* __restrict__ x_t, const float* __restrict__ W2a)
{
    __shared__ __align__(16) float As[BK][BM + 4];
    __shared__ __align__(16) float Bs[BK][BN + 4];

    int tid = threadIdx.x;
    int m0 = blockIdx.y * BM;
    int n0 = blockIdx.x * BN;

    float acc[4][4] = {};
    int ty = tid >> 4, tx = tid & 15;
    int ai = tid >> 2, akq = (tid & 3) * 4;
    int bk = tid >> 4, bn = (tid & 15) * 4;

    const int KTOT = FDIM + F2;  // 384
    for (int kt = 0; kt < KTOT; kt += BK) {
        int r = m0 + ai;
        int gk = kt + akq;
        float4 av = make_float4(0.f, 0.f, 0.f, 0.f);
        if (r < T_N) {
            if (gk < FDIM)
                av = *reinterpret_cast<const float4*>(x_t + (size_t)r * FDIM + gk);
            else
                av = *reinterpret_cast<const float4*>(&g_aggH[(size_t)r * F2 + gk - FDIM]);
        }
        As[akq + 0][ai] = av.x; As[akq + 1][ai] = av.y;
        As[akq + 2][ai] = av.z; As[akq + 3][ai] = av.w;

        int gkb = kt + bk;
        float4 bv;
        if (gkb < FDIM)
            bv = *reinterpret_cast<const float4*>(W2a + (size_t)gkb * F4 + n0 + bn);
        else
            bv = *reinterpret_cast<const float4*>(&g_Wmid[(size_t)(gkb - FDIM) * F4 + n0 + bn]);
        *reinterpret_cast<float4*>(&Bs[bk][bn]) = bv;
        __syncthreads();

        #pragma unroll
        for (int kk = 0; kk < BK; kk++) {
            float4 a = *reinterpret_cast<const float4*>(&As[kk][ty * 4]);
            float4 b = *reinterpret_cast<const float4*>(&Bs[kk][tx * 4]);
            float ar[4] = {a.x, a.y, a.z, a.w};
            float br[4] = {b.x, b.y, b.z, b.w};
            #pragma unroll
            for (int i = 0; i < 4; i++)
                #pragma unroll
                for (int j = 0; j < 4; j++)
                    acc[i][j] = fmaf(ar[i], br[j], acc[i][j]);
        }
        __syncthreads();
    }

    #pragma unroll
    for (int i = 0; i < 4; i++) {
        int r = m0 + ty * 4 + i;
        if (r >= T_N) continue;
        float c = (float)g_cnt[r];
        #pragma unroll
        for (int j = 0; j < 4; j++) {
            int n = n0 + tx * 4 + j;
            float v = acc[i][j] + g_c2[n] + c * g_bvec[n];
            v = v >= 0.f ? v : SLOPE * v;
            g_h3[(size_t)r * F4 + n] = v;
        }
    }
}

// ---------------------------------------------------------------------------
// Node GEMM 2: g_h3[T,512] @ W2b[512,128], epilogue +b2b -> out (pre-BN y)
// ---------------------------------------------------------------------------
__global__ void __launch_bounds__(256) gemm_node2(
    const float* __restrict__ W2b, const float* __restrict__ b2b,
    float* __restrict__ out)
{
    __shared__ __align__(16) float As[BK][BM + 4];
    __shared__ __align__(16) float Bs[BK][BN + 4];

    int tid = threadIdx.x;
    int m0 = blockIdx.y * BM;
    int n0 = blockIdx.x * BN;

    float acc[4][4] = {};
    int ty = tid >> 4, tx = tid & 15;
    int ai = tid >> 2, akq = (tid & 3) * 4;
    int bk = tid >> 4, bn = (tid & 15) * 4;

    for (int kt = 0; kt < F4; kt += BK) {
        int r = m0 + ai;
        float4 av = make_float4(0.f, 0.f, 0.f, 0.f);
        if (r < T_N)
            av = *reinterpret_cast<const float4*>(&g_h3[(size_t)r * F4 + kt + akq]);
        As[akq + 0][ai] = av.x; As[akq + 1][ai] = av.y;
        As[akq + 2][ai] = av.z; As[akq + 3][ai] = av.w;

        float4 bv = *reinterpret_cast<const float4*>(W2b + (size_t)(kt + bk) * FDIM + n0 + bn);
        *reinterpret_cast<float4*>(&Bs[bk][bn]) = bv;
        __syncthreads();

        #pragma unroll
        for (int kk = 0; kk < BK; kk++) {
            float4 a = *reinterpret_cast<const float4*>(&As[kk][ty * 4]);
            float4 b = *reinterpret_cast<const float4*>(&Bs[kk][tx * 4]);
            float ar[4] = {a.x, a.y, a.z, a.w};
            float br[4] = {b.x, b.y, b.z, b.w};
            #pragma unroll
            for (int i = 0; i < 4; i++)
                #pragma unroll
                for (int j = 0; j < 4; j++)
                    acc[i][j] = fmaf(ar[i], br[j], acc[i][j]);
        }
        __syncthreads();
    }

    #pragma unroll
    for (int i = 0; i < 4; i++) {
        int r = m0 + ty * 4 + i;
        if (r >= T_N) continue;
        #pragma unroll
        for (int j = 0; j < 4; j++) {
            int n = n0 + tx * 4 + j;
            out[(size_t)r * FDIM + n] = acc[i][j] + b2b[n];
        }
    }
}

// ---------------------------------------------------------------------------
// BatchNorm: column stats (double accum) then normalize in place
// ---------------------------------------------------------------------------
__global__ void bn_stats(const float* __restrict__ y) {
    int c = threadIdx.x & (FDIM - 1);
    int half = threadIdx.x >> 7;
    double s = 0.0, sq = 0.0;
    for (int m = blockIdx.x * 2 + half; m < T_N; m += gridDim.x * 2) {
        float v = y[(size_t)m * FDIM + c];
        s += v;
        sq += (double)v * (double)v;
    }
    atomicAdd(&g_sum[c], s);
    atomicAdd(&g_sumsq[c], sq);
}

__global__ void bn_norm(float* __restrict__ y,
                        const float* __restrict__ gamma,
                        const float* __restrict__ beta) {
    size_t idx = (size_t)blockIdx.x * blockDim.x + threadIdx.x;
    if (idx >= (size_t)T_N * FDIM) return;
    int c = (int)(idx & (FDIM - 1));
    double mean = g_sum[c] / (double)T_N;
    double var = g_sumsq[c] / (double)T_N - mean * mean;
    float scale = rsqrtf((float)var + BN_EPS) * gamma[c];
    y[idx] = (float)((double)y[idx] - mean) * scale + beta[c];
}

extern "C" void kernel_launch(void* const* d_in, const int* in_sizes, int n_in,
                              void* d_out, int out_size) {
    const float* x_s       = (const float*)d_in[0];
    const float* x_t       = (const float*)d_in[1];
    const float* edge_attr = (const float*)d_in[2];
    const float* u         = (const float*)d_in[3];
    const int*   eidx      = (const int*)d_in[4];
    const float* W1a       = (const float*)d_in[5];
    const float* b1a       = (const float*)d_in[6];
    const float* W1b       = (const float*)d_in[7];
    const float* b1b       = (const float*)d_in[8];
    const float* W2a       = (const float*)d_in[9];
    const float* b2a       = (const float*)d_in[10];
    const float* W2b       = (const float*)d_in[11];
    const float* b2b       = (const float*)d_in[12];
    const float* gamma     = (const float*)d_in[13];
    const float* beta      = (const float*)d_in[14];
    float* out = (float*)d_out;

    zero_kernel<<<1024, 256>>>();
    compute_Wmid<<<F2, 512>>>(W1b, W2a);
    compute_vecs<<<1, 512>>>(b1b, u, W2a, b2a);

    int sblk = (S_N + BM - 1) / BM;             // 782
    dim3 gP(F2 / BN, sblk);
    gemm_pre<<<gP, 256>>>(x_s, W1a, b1a);

    dim3 gE(F2 / BN, E_N / BM);                 // (4, 9375)
    gemm_edge<<<gE, 256>>>(edge_attr, eidx, W1a);

    int mblk = (T_N + BM - 1) / BM;             // 782
    dim3 gN1(F4 / BN, mblk);
    gemm_node1<<<gN1, 256>>>(x_t, W2a);

    dim3 gN2(FDIM / BN, mblk);
    gemm_node2<<<gN2, 256>>>(W2b, b2b, out);

    bn_stats<<<512, 256>>>(out);
    bn_norm<<<(T_N * FDIM + 255) / 256, 256>>>(out, gamma, beta);
}